// round 1
// baseline (speedup 1.0000x reference)
#include <cuda_runtime.h>

// Fused window cross-attention, one CTA per window (fp32 baseline).
// Phases per window:
//   0: load kv rows -> smem
//   1: kv projection -> K,V in smem
//   2: per 32-row q chunk: load q, q-proj, per-row attention (softmax+bias), out-proj
namespace {
constexpr int NKEY = 49;
constexpr int QN_  = 196;
constexpr int DIM_ = 384;
constexpr int NH_  = 12;
constexpr int HD_  = 32;
constexpr int CQ_  = 192;   // q input dim and output dim
constexpr float SCALE_ = 0.17677669529663687f;  // 32^-0.5

constexpr int SKV   = 385;  // padded stride (385 % 32 == 1 -> conflict-free)
constexpr int NT    = 256;
constexpr int CHUNK = 32;

// smem layout in floats
constexpr int OFF_K   = 0;
constexpr int OFF_V   = NKEY * SKV;
constexpr int OFF_R1  = 2 * NKEY * SKV;          // scratch region, 49*384 floats
constexpr int OFF_QIN = OFF_R1;                  // chunk q input: 32*192
constexpr int OFF_QP  = OFF_R1 + CHUNK * CQ_;    // chunk qp / o rows: 32*384
constexpr int OFF_P   = OFF_R1 + NKEY * DIM_;    // per-warp softmax probs: 8*64
constexpr int SMEM_FLOATS = OFF_P + 8 * 64;      // 57,058 floats = 228,232 B
}

__device__ __forceinline__ int rel_bias_idx(int qr, int key) {
    // query qr in 0..195 on the 14x14 grid; key in 0..48 maps to grid pos 4*key
    int qi = qr / 14, qj = qr - qi * 14;
    int kp = key * 4;
    int ki = kp / 14, kj = kp - ki * 14;
    int dh = (qi >> 1) - (ki >> 1) + 6;
    int dw = (qj >> 1) - (kj >> 1) + 6;
    return dh * 13 + dw;
}

__global__ __launch_bounds__(NT, 1)
void wca_kernel(const float* __restrict__ kv, const float* __restrict__ q,
                const float* __restrict__ w_kv, const float* __restrict__ b_kv,
                const float* __restrict__ w_q, const float* __restrict__ b_q,
                const float* __restrict__ bias_table,
                const float* __restrict__ w_proj, const float* __restrict__ b_proj,
                float* __restrict__ out)
{
    extern __shared__ float smf[];
    float* s_k   = smf + OFF_K;
    float* s_v   = smf + OFF_V;
    float* s_r1  = smf + OFF_R1;
    float* s_qin = smf + OFF_QIN;
    float* s_qp  = smf + OFF_QP;
    float* s_p   = smf + OFF_P;

    const int b   = blockIdx.x;
    const int tid = threadIdx.x;

    // ---- phase 0: load kv rows (49x384) ----
    const float* kvb = kv + (size_t)b * (NKEY * DIM_);
    for (int i = tid; i < NKEY * DIM_; i += NT) s_r1[i] = kvb[i];
    __syncthreads();

    // ---- phase 1: kv projection -> K (cols 0..383), V (cols 384..767) ----
    {
        const int c0 = tid, c1 = tid + 256, c2 = tid + 512;
        const float bb0 = b_kv[c0], bb1 = b_kv[c1], bb2 = b_kv[c2];
        for (int g = 0; g < 4; ++g) {
            const int n0 = g * 16;
            const int cnt = (NKEY - n0) < 16 ? (NKEY - n0) : 16;
            if (cnt == 16) {
                float a0[16], a1[16], a2[16];
                #pragma unroll
                for (int r = 0; r < 16; ++r) { a0[r] = bb0; a1[r] = bb1; a2[r] = bb2; }
                #pragma unroll 2
                for (int k = 0; k < DIM_; ++k) {
                    const float w0 = w_kv[k * 768 + c0];
                    const float w1 = w_kv[k * 768 + c1];
                    const float w2 = w_kv[k * 768 + c2];
                    const float* xr = s_r1 + n0 * DIM_ + k;
                    #pragma unroll
                    for (int r = 0; r < 16; ++r) {
                        const float x = xr[r * DIM_];
                        a0[r] = fmaf(x, w0, a0[r]);
                        a1[r] = fmaf(x, w1, a1[r]);
                        a2[r] = fmaf(x, w2, a2[r]);
                    }
                }
                #pragma unroll
                for (int r = 0; r < 16; ++r) {
                    const int n = n0 + r;
                    s_k[n * SKV + c0] = a0[r];
                    if (c1 < DIM_) s_k[n * SKV + c1] = a1[r];
                    else           s_v[n * SKV + (c1 - DIM_)] = a1[r];
                    s_v[n * SKV + (c2 - DIM_)] = a2[r];
                }
            } else {
                for (int r = 0; r < cnt; ++r) {
                    const int n = n0 + r;
                    float a0 = bb0, a1 = bb1, a2 = bb2;
                    const float* xr = s_r1 + n * DIM_;
                    for (int k = 0; k < DIM_; ++k) {
                        const float x = xr[k];
                        a0 = fmaf(x, w_kv[k * 768 + c0], a0);
                        a1 = fmaf(x, w_kv[k * 768 + c1], a1);
                        a2 = fmaf(x, w_kv[k * 768 + c2], a2);
                    }
                    s_k[n * SKV + c0] = a0;
                    if (c1 < DIM_) s_k[n * SKV + c1] = a1;
                    else           s_v[n * SKV + (c1 - DIM_)] = a1;
                    s_v[n * SKV + (c2 - DIM_)] = a2;
                }
            }
        }
    }
    __syncthreads();

    // ---- phase 2: q chunks ----
    const int wi = tid >> 5, lane = tid & 31;
    for (int q0 = 0; q0 < QN_; q0 += CHUNK) {
        const int nr = (QN_ - q0) < CHUNK ? (QN_ - q0) : CHUNK;

        // 2a: load q chunk
        const float* qb = q + (size_t)b * (QN_ * CQ_) + (size_t)q0 * CQ_;
        for (int i = tid; i < nr * CQ_; i += NT) s_qin[i] = qb[i];
        __syncthreads();

        // 2b: q projection -> s_qp[r][0..383]
        if (tid < 192) {
            const int c0 = tid, c1 = tid + 192;
            const float bq0 = b_q[c0], bq1 = b_q[c1];
            for (int g = 0; g < 2; ++g) {
                const int r0 = g * 16;
                const int cnt = min(16, nr - r0);
                if (cnt <= 0) break;
                if (cnt == 16) {
                    float a0[16], a1[16];
                    #pragma unroll
                    for (int r = 0; r < 16; ++r) { a0[r] = bq0; a1[r] = bq1; }
                    #pragma unroll 2
                    for (int k = 0; k < CQ_; ++k) {
                        const float w0 = w_q[k * DIM_ + c0];
                        const float w1 = w_q[k * DIM_ + c1];
                        const float* xr = s_qin + r0 * CQ_ + k;
                        #pragma unroll
                        for (int r = 0; r < 16; ++r) {
                            const float x = xr[r * CQ_];
                            a0[r] = fmaf(x, w0, a0[r]);
                            a1[r] = fmaf(x, w1, a1[r]);
                        }
                    }
                    #pragma unroll
                    for (int r = 0; r < 16; ++r) {
                        s_qp[(r0 + r) * DIM_ + c0] = a0[r];
                        s_qp[(r0 + r) * DIM_ + c1] = a1[r];
                    }
                } else {
                    for (int r = 0; r < cnt; ++r) {
                        float a0 = bq0, a1 = bq1;
                        const float* xr = s_qin + (r0 + r) * CQ_;
                        for (int k = 0; k < CQ_; ++k) {
                            const float x = xr[k];
                            a0 = fmaf(x, w_q[k * DIM_ + c0], a0);
                            a1 = fmaf(x, w_q[k * DIM_ + c1], a1);
                        }
                        s_qp[(r0 + r) * DIM_ + c0] = a0;
                        s_qp[(r0 + r) * DIM_ + c1] = a1;
                    }
                }
            }
        }
        __syncthreads();

        // 2c: attention, warp per q row; o overwrites qp row in place per head
        {
            const int key2  = 32 + lane;
            const bool v2   = key2 < NKEY;          // lanes 0..16 hold a 2nd key
            const int key2c = v2 ? key2 : 0;
            for (int r = wi; r < nr; r += 8) {
                const int qr  = q0 + r;
                const int bi1 = rel_bias_idx(qr, lane) * NH_;
                const int bi2 = rel_bias_idx(qr, key2c) * NH_;
                float* qprow = s_qp + r * DIM_;
                for (int h = 0; h < NH_; ++h) {
                    const int base = h * HD_;
                    const float* kp1 = s_k + lane  * SKV + base;
                    const float* kp2 = s_k + key2c * SKV + base;
                    float l1 = 0.f, l2 = 0.f;
                    #pragma unroll
                    for (int d = 0; d < HD_; ++d) {
                        const float qv = qprow[base + d];
                        l1 = fmaf(qv, kp1[d], l1);
                        l2 = fmaf(qv, kp2[d], l2);
                    }
                    l1 = l1 * SCALE_ + bias_table[bi1 + h];
                    l2 = v2 ? (l2 * SCALE_ + bias_table[bi2 + h]) : -1e30f;
                    float m = fmaxf(l1, l2);
                    #pragma unroll
                    for (int o = 16; o; o >>= 1)
                        m = fmaxf(m, __shfl_xor_sync(0xffffffffu, m, o));
                    const float p1 = __expf(l1 - m);
                    const float p2 = v2 ? __expf(l2 - m) : 0.f;
                    float ssum = p1 + p2;
                    #pragma unroll
                    for (int o = 16; o; o >>= 1)
                        ssum += __shfl_xor_sync(0xffffffffu, ssum, o);
                    const float inv = 1.0f / ssum;
                    s_p[wi * 64 + lane]      = p1 * inv;
                    s_p[wi * 64 + 32 + lane] = p2 * inv;
                    __syncwarp();
                    // AV: lane == head dim d
                    float oacc = 0.f;
                    const float* vp = s_v + base + lane;
                    const float* pp = s_p + wi * 64;
                    #pragma unroll
                    for (int k = 0; k < NKEY; ++k)
                        oacc = fmaf(pp[k], vp[k * SKV], oacc);
                    __syncwarp();
                    qprow[base + lane] = oacc;   // overwrite qp head-h slot with o
                }
            }
        }
        __syncthreads();

        // 2d: output projection o(384) @ w_proj(384x192) + b_proj -> gmem
        if (tid < 192) {
            const int j = tid;
            const float bp = b_proj[j];
            for (int g = 0; g < 2; ++g) {
                const int r0 = g * 16;
                const int cnt = min(16, nr - r0);
                if (cnt <= 0) break;
                if (cnt == 16) {
                    float acc[16];
                    #pragma unroll
                    for (int r = 0; r < 16; ++r) acc[r] = bp;
                    #pragma unroll 2
                    for (int c = 0; c < DIM_; ++c) {
                        const float w = w_proj[c * CQ_ + j];
                        const float* xr = s_qp + r0 * DIM_ + c;
                        #pragma unroll
                        for (int r = 0; r < 16; ++r)
                            acc[r] = fmaf(xr[r * DIM_], w, acc[r]);
                    }
                    float* ob = out + (size_t)b * (QN_ * CQ_) + (size_t)(q0 + r0) * CQ_ + j;
                    #pragma unroll
                    for (int r = 0; r < 16; ++r) ob[r * CQ_] = acc[r];
                } else {
                    for (int r = 0; r < cnt; ++r) {
                        float acc = bp;
                        const float* xr = s_qp + (r0 + r) * DIM_;
                        for (int c = 0; c < DIM_; ++c)
                            acc = fmaf(xr[c], w_proj[c * CQ_ + j], acc);
                        out[(size_t)b * (QN_ * CQ_) + (size_t)(q0 + r0 + r) * CQ_ + j] = acc;
                    }
                }
            }
        }
        __syncthreads();
    }
}

extern "C" void kernel_launch(void* const* d_in, const int* in_sizes, int n_in,
                              void* d_out, int out_size) {
    const float* kv         = (const float*)d_in[0];
    const float* q          = (const float*)d_in[1];
    const float* w_kv       = (const float*)d_in[2];
    const float* b_kv       = (const float*)d_in[3];
    const float* w_q        = (const float*)d_in[4];
    const float* b_q        = (const float*)d_in[5];
    const float* bias_table = (const float*)d_in[6];
    const float* w_proj     = (const float*)d_in[7];
    const float* b_proj     = (const float*)d_in[8];
    float* out = (float*)d_out;

    const int B = in_sizes[0] / (NKEY * DIM_);   // 2048
    const size_t smem = (size_t)SMEM_FLOATS * sizeof(float);  // 228,232 B
    cudaFuncSetAttribute(wca_kernel, cudaFuncAttributeMaxDynamicSharedMemorySize, (int)smem);
    wca_kernel<<<B, NT, smem>>>(kv, q, w_kv, b_kv, w_q, b_q, bias_table,
                                w_proj, b_proj, out);
}